// round 3
// baseline (speedup 1.0000x reference)
#include <cuda_runtime.h>

// ---------------------------------------------------------------------------
// OTPE single timestep.
// Inputs (metadata order): x[8192], W[8192,4096], u[4096], E[8192,4096],
//                          R_hat[8192,4096], g_bar[4096], ratio[1]
// Output (flattened tuple): s[4096], u_new[4096], E_new[8192*4096],
//                           R_new[8192*4096], g_bar_new[4096], ratio_new[1]
// ---------------------------------------------------------------------------

#define N_IN   8192
#define N_OUT  4096
#define N_OUTV (N_OUT / 4)               // 1024 float4 per row
// sigmoid(2.0) in fp32
#define SIG_TAU 0.88079707797788231f

#define NSPLIT 256
#define ROWS_PER_SPLIT (N_IN / NSPLIT)   // 32

// scratch (device globals; no allocation allowed)
__device__ __align__(16) float g_part[NSPLIT * N_OUT];   // 4 MB
__device__ __align__(16) float g_sg[N_OUT];

// ---------------------------------------------------------------------------
// K1: split-K GEMV partials, float4-vectorized over columns.
// grid (8, 256) = 2048 blocks, block 128. Each thread owns 4 adjacent output
// columns within one 32-row split. Loads batched 4 deep for per-thread MLP.
// ---------------------------------------------------------------------------
__global__ void __launch_bounds__(128)
otpe_gemv_partial(const float4* __restrict__ W4, const float* __restrict__ x) {
    __shared__ float sx[ROWS_PER_SPLIT];
    const int colv  = blockIdx.x * 128 + threadIdx.x;   // 0..1023
    const int split = blockIdx.y;
    const int r0    = split * ROWS_PER_SPLIT;

    if (threadIdx.x < ROWS_PER_SPLIT)
        sx[threadIdx.x] = x[r0 + threadIdx.x];
    __syncthreads();

    const float4* Wp = W4 + (size_t)r0 * N_OUTV + colv;

    float4 a0 = make_float4(0.f, 0.f, 0.f, 0.f);
    float4 a1 = make_float4(0.f, 0.f, 0.f, 0.f);

#pragma unroll
    for (int r = 0; r < ROWS_PER_SPLIT; r += 4) {
        const float4 w0 = Wp[(size_t)(r + 0) * N_OUTV];
        const float4 w1 = Wp[(size_t)(r + 1) * N_OUTV];
        const float4 w2 = Wp[(size_t)(r + 2) * N_OUTV];
        const float4 w3 = Wp[(size_t)(r + 3) * N_OUTV];
        const float x0 = sx[r + 0], x1 = sx[r + 1];
        const float x2 = sx[r + 2], x3 = sx[r + 3];

        a0.x = fmaf(x0, w0.x, a0.x); a0.y = fmaf(x0, w0.y, a0.y);
        a0.z = fmaf(x0, w0.z, a0.z); a0.w = fmaf(x0, w0.w, a0.w);
        a1.x = fmaf(x1, w1.x, a1.x); a1.y = fmaf(x1, w1.y, a1.y);
        a1.z = fmaf(x1, w1.z, a1.z); a1.w = fmaf(x1, w1.w, a1.w);
        a0.x = fmaf(x2, w2.x, a0.x); a0.y = fmaf(x2, w2.y, a0.y);
        a0.z = fmaf(x2, w2.z, a0.z); a0.w = fmaf(x2, w2.w, a0.w);
        a1.x = fmaf(x3, w3.x, a1.x); a1.y = fmaf(x3, w3.y, a1.y);
        a1.z = fmaf(x3, w3.z, a1.z); a1.w = fmaf(x3, w3.w, a1.w);
    }

    float4 out;
    out.x = a0.x + a1.x; out.y = a0.y + a1.y;
    out.z = a0.z + a1.z; out.w = a0.w + a1.w;
    reinterpret_cast<float4*>(g_part)[split * N_OUTV + colv] = out;
}

// ---------------------------------------------------------------------------
// K2: deterministic reduce over 256 splits + per-column post, float4 wide.
// grid 8, block 128 (1024 threads, one float4 column-group each).
// Partials are L2-resident from K1.
// ---------------------------------------------------------------------------
__global__ void __launch_bounds__(128)
otpe_column_post(const float* __restrict__ u,
                 const float* __restrict__ g_bar,
                 const float* __restrict__ ratio,
                 float* __restrict__ out_s,
                 float* __restrict__ out_u,
                 float* __restrict__ out_gbar,
                 float* __restrict__ out_ratio) {
    const int jv = blockIdx.x * 128 + threadIdx.x;      // 0..1023
    const float4* P4 = reinterpret_cast<const float4*>(g_part);

    float4 a0 = make_float4(0.f, 0.f, 0.f, 0.f);
    float4 a1 = make_float4(0.f, 0.f, 0.f, 0.f);
#pragma unroll 8
    for (int s = 0; s < NSPLIT; s += 2) {
        const float4 p0 = P4[(size_t)(s + 0) * N_OUTV + jv];
        const float4 p1 = P4[(size_t)(s + 1) * N_OUTV + jv];
        a0.x += p0.x; a0.y += p0.y; a0.z += p0.z; a0.w += p0.w;
        a1.x += p1.x; a1.y += p1.y; a1.z += p1.z; a1.w += p1.w;
    }
    const float4 uu = reinterpret_cast<const float4*>(u)[jv];
    float up[4];
    up[0] = fmaf(SIG_TAU, uu.x, a0.x + a1.x);
    up[1] = fmaf(SIG_TAU, uu.y, a0.y + a1.y);
    up[2] = fmaf(SIG_TAU, uu.z, a0.z + a1.z);
    up[3] = fmaf(SIG_TAU, uu.w, a0.w + a1.w);

    const float r0        = SIG_TAU * ratio[0];
    const float ratio_new = r0 + 1.0f;
    const float rw        = r0 / ratio_new;
    const float4 gb = reinterpret_cast<const float4*>(g_bar)[jv];
    const float gbv[4] = {gb.x, gb.y, gb.z, gb.w};

    float4 s4, u4, sg4, gb4;
    float* sp  = &s4.x;  float* upo = &u4.x;
    float* sgp = &sg4.x; float* gbp = &gb4.x;
#pragma unroll
    for (int k = 0; k < 4; ++k) {
        const float u_pre = up[k];
        const float spike = (u_pre >= 1.0f) ? 1.0f : 0.0f;
        const float t  = fmaf(10.0f, fabsf(u_pre - 1.0f), 1.0f);
        const float sg = 1.0f / (t * t);
        sp[k]  = spike;
        upo[k] = u_pre - spike;                    // soft reset (V_TH = 1)
        sgp[k] = sg;
        gbp[k] = fmaf(rw, gbv[k], (1.0f - rw) * sg);  // ds_du_prev/sig = sg
    }

    reinterpret_cast<float4*>(g_sg)[jv]     = sg4;
    reinterpret_cast<float4*>(out_s)[jv]    = s4;
    reinterpret_cast<float4*>(out_u)[jv]    = u4;
    reinterpret_cast<float4*>(out_gbar)[jv] = gb4;
    if (jv == 0) out_ratio[0] = ratio_new;
}

// ---------------------------------------------------------------------------
// K3: fused E/R update, float4 vectorized, 2 vector-pairs per thread,
// evict-streaming loads/stores (zero-reuse data). grid 16384, block 256.
// ---------------------------------------------------------------------------
__global__ void __launch_bounds__(256)
otpe_big_elem(const float4* __restrict__ E,
              const float4* __restrict__ R,
              const float*  __restrict__ x,
              float4* __restrict__ Eo,
              float4* __restrict__ Ro) {
    // each block covers 512 consecutive float4: two 256-wide chunks
    const long long base = (long long)blockIdx.x * 512 + threadIdx.x;

#pragma unroll
    for (int h = 0; h < 2; ++h) {
        const long long v = base + h * 256;
        const int row  = (int)(v >> 10);        // 1024 float4 per row
        const int colv = (int)(v & 1023);

        const float  xi  = __ldg(&x[row]);
        const float4 sg4 = reinterpret_cast<const float4*>(g_sg)[colv];
        const float4 e   = __ldcs(&E[v]);
        const float4 rr  = __ldcs(&R[v]);

        float4 eo, ro;
        eo.x = fmaf(SIG_TAU, e.x, xi);
        eo.y = fmaf(SIG_TAU, e.y, xi);
        eo.z = fmaf(SIG_TAU, e.z, xi);
        eo.w = fmaf(SIG_TAU, e.w, xi);

        // R_new = sig*R + (sg*sig)*E_old + x*sg
        ro.x = fmaf(SIG_TAU, rr.x, fmaf(sg4.x * SIG_TAU, e.x, xi * sg4.x));
        ro.y = fmaf(SIG_TAU, rr.y, fmaf(sg4.y * SIG_TAU, e.y, xi * sg4.y));
        ro.z = fmaf(SIG_TAU, rr.z, fmaf(sg4.z * SIG_TAU, e.z, xi * sg4.z));
        ro.w = fmaf(SIG_TAU, rr.w, fmaf(sg4.w * SIG_TAU, e.w, xi * sg4.w));

        __stcs(&Eo[v], eo);
        __stcs(&Ro[v], ro);
    }
}

// ---------------------------------------------------------------------------
extern "C" void kernel_launch(void* const* d_in, const int* in_sizes, int n_in,
                              void* d_out, int out_size) {
    const float* x     = (const float*)d_in[0];
    const float* W     = (const float*)d_in[1];
    const float* u     = (const float*)d_in[2];
    const float* E     = (const float*)d_in[3];
    const float* R     = (const float*)d_in[4];
    const float* g_bar = (const float*)d_in[5];
    const float* ratio = (const float*)d_in[6];

    float* out       = (float*)d_out;
    float* out_s     = out;
    float* out_u     = out + N_OUT;
    float* out_E     = out + 2 * N_OUT;
    float* out_R     = out_E + (size_t)N_IN * N_OUT;
    float* out_gbar  = out_R + (size_t)N_IN * N_OUT;
    float* out_ratio = out_gbar + N_OUT;

    otpe_gemv_partial<<<dim3(N_OUTV / 128, NSPLIT), 128>>>((const float4*)W, x);
    otpe_column_post<<<N_OUTV / 128, 128>>>(u, g_bar, ratio,
                                            out_s, out_u, out_gbar, out_ratio);

    const long long nvec = (long long)N_IN * N_OUT / 4;   // 8388608
    otpe_big_elem<<<(unsigned)(nvec / 512), 256>>>(
        (const float4*)E, (const float4*)R, x,
        (float4*)out_E, (float4*)out_R);
}

// round 4
// speedup vs baseline: 1.1675x; 1.1675x over previous
#include <cuda_runtime.h>

// ---------------------------------------------------------------------------
// OTPE single timestep.
// Inputs (metadata order): x[8192], W[8192,4096], u[4096], E[8192,4096],
//                          R_hat[8192,4096], g_bar[4096], ratio[1]
// Output (flattened tuple): s[4096], u_new[4096], E_new[8192*4096],
//                           R_new[8192*4096], g_bar_new[4096], ratio_new[1]
// ---------------------------------------------------------------------------

#define N_IN   8192
#define N_OUT  4096
#define N_OUTV (N_OUT / 4)               // 1024 float4 per row
// sigmoid(2.0) in fp32
#define SIG_TAU 0.88079707797788231f

#define NSPLIT 512
#define ROWS_PER_SPLIT (N_IN / NSPLIT)   // 16
#define NGROUP 16                        // stage-2 reduce groups
#define SPLITS_PER_GROUP (NSPLIT / NGROUP) // 32

// scratch (device globals; no allocation allowed)
__device__ __align__(16) float g_part[NSPLIT * N_OUT];    // 8 MB
__device__ __align__(16) float g_part2[NGROUP * N_OUT];   // 256 KB
__device__ __align__(16) float g_sg[N_OUT];

// ---------------------------------------------------------------------------
// K1: split-K GEMV partials. grid (2, 512) = 1024 blocks, block 256.
// Thread t owns float4 columns (bx*512 + t) and (bx*512 + t + 256):
// each block covers two 4KB-contiguous spans per row (8KB/row), 16 rows.
// 4 LDG.128 batched per 2-row step for MLP.
// ---------------------------------------------------------------------------
__global__ void __launch_bounds__(256)
otpe_gemv_partial(const float4* __restrict__ W4, const float* __restrict__ x) {
    __shared__ float sx[ROWS_PER_SPLIT];
    const int t     = threadIdx.x;
    const int c0    = blockIdx.x * 512 + t;       // first colv
    const int split = blockIdx.y;
    const int r0    = split * ROWS_PER_SPLIT;

    if (t < ROWS_PER_SPLIT)
        sx[t] = x[r0 + t];
    __syncthreads();

    const float4* Wp = W4 + (size_t)r0 * N_OUTV;

    float4 A0 = make_float4(0.f, 0.f, 0.f, 0.f);
    float4 A1 = make_float4(0.f, 0.f, 0.f, 0.f);

#pragma unroll
    for (int r = 0; r < ROWS_PER_SPLIT; r += 2) {
        const float4 w00 = Wp[(size_t)(r + 0) * N_OUTV + c0];
        const float4 w01 = Wp[(size_t)(r + 0) * N_OUTV + c0 + 256];
        const float4 w10 = Wp[(size_t)(r + 1) * N_OUTV + c0];
        const float4 w11 = Wp[(size_t)(r + 1) * N_OUTV + c0 + 256];
        const float xa = sx[r], xb = sx[r + 1];

        A0.x = fmaf(xa, w00.x, A0.x); A0.y = fmaf(xa, w00.y, A0.y);
        A0.z = fmaf(xa, w00.z, A0.z); A0.w = fmaf(xa, w00.w, A0.w);
        A1.x = fmaf(xa, w01.x, A1.x); A1.y = fmaf(xa, w01.y, A1.y);
        A1.z = fmaf(xa, w01.z, A1.z); A1.w = fmaf(xa, w01.w, A1.w);
        A0.x = fmaf(xb, w10.x, A0.x); A0.y = fmaf(xb, w10.y, A0.y);
        A0.z = fmaf(xb, w10.z, A0.z); A0.w = fmaf(xb, w10.w, A0.w);
        A1.x = fmaf(xb, w11.x, A1.x); A1.y = fmaf(xb, w11.y, A1.y);
        A1.z = fmaf(xb, w11.z, A1.z); A1.w = fmaf(xb, w11.w, A1.w);
    }

    float4* P = reinterpret_cast<float4*>(g_part) + (size_t)split * N_OUTV;
    P[c0]       = A0;
    P[c0 + 256] = A1;
}

// ---------------------------------------------------------------------------
// K2a: stage-1 reduce, 512 splits -> 16 groups. grid (16,16), block 256.
// 65536 threads, 32 L2-resident loads each (4 accumulators for MLP).
// ---------------------------------------------------------------------------
__global__ void __launch_bounds__(256)
otpe_reduce1() {
    const int col = blockIdx.x * 256 + threadIdx.x;   // 0..4095
    const int g   = blockIdx.y;                        // 0..15
    const int s0  = g * SPLITS_PER_GROUP;

    float a0 = 0.f, a1 = 0.f, a2 = 0.f, a3 = 0.f;
#pragma unroll
    for (int s = 0; s < SPLITS_PER_GROUP; s += 4) {
        a0 += g_part[(size_t)(s0 + s + 0) * N_OUT + col];
        a1 += g_part[(size_t)(s0 + s + 1) * N_OUT + col];
        a2 += g_part[(size_t)(s0 + s + 2) * N_OUT + col];
        a3 += g_part[(size_t)(s0 + s + 3) * N_OUT + col];
    }
    g_part2[g * N_OUT + col] = (a0 + a1) + (a2 + a3);
}

// ---------------------------------------------------------------------------
// K2b: stage-2 reduce (16 groups) + per-column post. grid 16, block 256.
// ---------------------------------------------------------------------------
__global__ void __launch_bounds__(256)
otpe_column_post(const float* __restrict__ u,
                 const float* __restrict__ g_bar,
                 const float* __restrict__ ratio,
                 float* __restrict__ out_s,
                 float* __restrict__ out_u,
                 float* __restrict__ out_gbar,
                 float* __restrict__ out_ratio) {
    const int j = blockIdx.x * 256 + threadIdx.x;     // 0..4095

    float a0 = SIG_TAU * u[j], a1 = 0.f, a2 = 0.f, a3 = 0.f;
#pragma unroll
    for (int g = 0; g < NGROUP; g += 4) {
        a0 += g_part2[(g + 0) * N_OUT + j];
        a1 += g_part2[(g + 1) * N_OUT + j];
        a2 += g_part2[(g + 2) * N_OUT + j];
        a3 += g_part2[(g + 3) * N_OUT + j];
    }
    const float u_pre = (a0 + a1) + (a2 + a3);

    const float spike = (u_pre >= 1.0f) ? 1.0f : 0.0f;
    const float t  = fmaf(10.0f, fabsf(u_pre - 1.0f), 1.0f);
    const float sg = 1.0f / (t * t);

    g_sg[j]  = sg;
    out_s[j] = spike;
    out_u[j] = u_pre - spike;          // soft reset (V_TH = 1)

    const float r0        = SIG_TAU * ratio[0];
    const float ratio_new = r0 + 1.0f;
    const float r         = r0 / ratio_new;
    // ds_du_prev / sig_tau == sg
    out_gbar[j] = fmaf(r, g_bar[j], (1.0f - r) * sg);

    if (j == 0) out_ratio[0] = ratio_new;
}

// ---------------------------------------------------------------------------
// K3: fused E/R update (exact R1 structure), float4, 1 per thread.
// R_new = sig*R_hat + sg*E_new  (identity: sg*(sig*E + x) = ds_dtheta).
// grid 32768, block 256.
// ---------------------------------------------------------------------------
__global__ void __launch_bounds__(256)
otpe_big_elem(const float4* __restrict__ E,
              const float4* __restrict__ R,
              const float*  __restrict__ x,
              float4* __restrict__ Eo,
              float4* __restrict__ Ro) {
    const long long v = (long long)blockIdx.x * 256 + threadIdx.x;
    const int row  = (int)(v >> 10);        // 1024 float4 per row
    const int colv = (int)(v & 1023);

    const float  xi  = __ldg(&x[row]);
    const float4 sg4 = reinterpret_cast<const float4*>(g_sg)[colv];
    const float4 e   = E[v];
    const float4 rr  = R[v];

    float4 eo, ro;
    eo.x = fmaf(SIG_TAU, e.x, xi);
    eo.y = fmaf(SIG_TAU, e.y, xi);
    eo.z = fmaf(SIG_TAU, e.z, xi);
    eo.w = fmaf(SIG_TAU, e.w, xi);

    ro.x = fmaf(sg4.x, eo.x, SIG_TAU * rr.x);
    ro.y = fmaf(sg4.y, eo.y, SIG_TAU * rr.y);
    ro.z = fmaf(sg4.z, eo.z, SIG_TAU * rr.z);
    ro.w = fmaf(sg4.w, eo.w, SIG_TAU * rr.w);

    Eo[v] = eo;
    Ro[v] = ro;
}

// ---------------------------------------------------------------------------
extern "C" void kernel_launch(void* const* d_in, const int* in_sizes, int n_in,
                              void* d_out, int out_size) {
    const float* x     = (const float*)d_in[0];
    const float* W     = (const float*)d_in[1];
    const float* u     = (const float*)d_in[2];
    const float* E     = (const float*)d_in[3];
    const float* R     = (const float*)d_in[4];
    const float* g_bar = (const float*)d_in[5];
    const float* ratio = (const float*)d_in[6];

    float* out       = (float*)d_out;
    float* out_s     = out;
    float* out_u     = out + N_OUT;
    float* out_E     = out + 2 * N_OUT;
    float* out_R     = out_E + (size_t)N_IN * N_OUT;
    float* out_gbar  = out_R + (size_t)N_IN * N_OUT;
    float* out_ratio = out_gbar + N_OUT;

    otpe_gemv_partial<<<dim3(2, NSPLIT), 256>>>((const float4*)W, x);
    otpe_reduce1<<<dim3(N_OUT / 256, NGROUP), 256>>>();
    otpe_column_post<<<N_OUT / 256, 256>>>(u, g_bar, ratio,
                                           out_s, out_u, out_gbar, out_ratio);

    const long long nvec = (long long)N_IN * N_OUT / 4;   // 8388608
    otpe_big_elem<<<(unsigned)(nvec / 256), 256>>>(
        (const float4*)E, (const float4*)R, x,
        (float4*)out_E, (float4*)out_R);
}

// round 5
// speedup vs baseline: 1.1678x; 1.0003x over previous
#include <cuda_runtime.h>

// ---------------------------------------------------------------------------
// OTPE single timestep.
// Inputs (metadata order): x[8192], W[8192,4096], u[4096], E[8192,4096],
//                          R_hat[8192,4096], g_bar[4096], ratio[1]
// Output (flattened tuple): s[4096], u_new[4096], E_new[8192*4096],
//                           R_new[8192*4096], g_bar_new[4096], ratio_new[1]
// ---------------------------------------------------------------------------

#define N_IN   8192
#define N_OUT  4096
#define N_OUTV (N_OUT / 4)               // 1024 float4 per row
// sigmoid(2.0) in fp32
#define SIG_TAU 0.88079707797788231f

#define NSPLIT 512
#define ROWS_PER_SPLIT (N_IN / NSPLIT)   // 16
#define NGROUP 16                        // stage-2 reduce groups
#define SPLITS_PER_GROUP (NSPLIT / NGROUP) // 32

// scratch (device globals; no allocation allowed)
__device__ __align__(16) float g_part[NSPLIT * N_OUT];    // 8 MB
__device__ __align__(16) float g_part2[NGROUP * N_OUT];   // 256 KB
__device__ __align__(16) float g_sg[N_OUT];

// ---------------------------------------------------------------------------
// K1: split-K GEMV partials. grid (2, 512) = 1024 blocks, block 256.
// Thread t owns float4 columns c0 and c0+256. Inner loop batches
// 4 rows x 2 cols = 8 LDG.128 in flight per warp before any FMA
// (Little's law: ~228 LDG.128/SM in flight needed for ~6.5TB/s).
// ---------------------------------------------------------------------------
__global__ void __launch_bounds__(256)
otpe_gemv_partial(const float4* __restrict__ W4, const float* __restrict__ x) {
    __shared__ float sx[ROWS_PER_SPLIT];
    const int t     = threadIdx.x;
    const int c0    = blockIdx.x * 512 + t;       // first colv
    const int split = blockIdx.y;
    const int r0    = split * ROWS_PER_SPLIT;

    if (t < ROWS_PER_SPLIT)
        sx[t] = x[r0 + t];
    __syncthreads();

    const float4* Wp = W4 + (size_t)r0 * N_OUTV;

    float4 A0 = make_float4(0.f, 0.f, 0.f, 0.f);
    float4 A1 = make_float4(0.f, 0.f, 0.f, 0.f);

#pragma unroll
    for (int r = 0; r < ROWS_PER_SPLIT; r += 4) {
        // 8 independent LDG.128 issued back-to-back
        const float4 w00 = Wp[(size_t)(r + 0) * N_OUTV + c0];
        const float4 w01 = Wp[(size_t)(r + 0) * N_OUTV + c0 + 256];
        const float4 w10 = Wp[(size_t)(r + 1) * N_OUTV + c0];
        const float4 w11 = Wp[(size_t)(r + 1) * N_OUTV + c0 + 256];
        const float4 w20 = Wp[(size_t)(r + 2) * N_OUTV + c0];
        const float4 w21 = Wp[(size_t)(r + 2) * N_OUTV + c0 + 256];
        const float4 w30 = Wp[(size_t)(r + 3) * N_OUTV + c0];
        const float4 w31 = Wp[(size_t)(r + 3) * N_OUTV + c0 + 256];
        const float xa = sx[r + 0], xb = sx[r + 1];
        const float xc = sx[r + 2], xd = sx[r + 3];

        A0.x = fmaf(xa, w00.x, A0.x); A0.y = fmaf(xa, w00.y, A0.y);
        A0.z = fmaf(xa, w00.z, A0.z); A0.w = fmaf(xa, w00.w, A0.w);
        A1.x = fmaf(xa, w01.x, A1.x); A1.y = fmaf(xa, w01.y, A1.y);
        A1.z = fmaf(xa, w01.z, A1.z); A1.w = fmaf(xa, w01.w, A1.w);
        A0.x = fmaf(xb, w10.x, A0.x); A0.y = fmaf(xb, w10.y, A0.y);
        A0.z = fmaf(xb, w10.z, A0.z); A0.w = fmaf(xb, w10.w, A0.w);
        A1.x = fmaf(xb, w11.x, A1.x); A1.y = fmaf(xb, w11.y, A1.y);
        A1.z = fmaf(xb, w11.z, A1.z); A1.w = fmaf(xb, w11.w, A1.w);
        A0.x = fmaf(xc, w20.x, A0.x); A0.y = fmaf(xc, w20.y, A0.y);
        A0.z = fmaf(xc, w20.z, A0.z); A0.w = fmaf(xc, w20.w, A0.w);
        A1.x = fmaf(xc, w21.x, A1.x); A1.y = fmaf(xc, w21.y, A1.y);
        A1.z = fmaf(xc, w21.z, A1.z); A1.w = fmaf(xc, w21.w, A1.w);
        A0.x = fmaf(xd, w30.x, A0.x); A0.y = fmaf(xd, w30.y, A0.y);
        A0.z = fmaf(xd, w30.z, A0.z); A0.w = fmaf(xd, w30.w, A0.w);
        A1.x = fmaf(xd, w31.x, A1.x); A1.y = fmaf(xd, w31.y, A1.y);
        A1.z = fmaf(xd, w31.z, A1.z); A1.w = fmaf(xd, w31.w, A1.w);
    }

    float4* P = reinterpret_cast<float4*>(g_part) + (size_t)split * N_OUTV;
    P[c0]       = A0;
    P[c0 + 256] = A1;
}

// ---------------------------------------------------------------------------
// K2a: stage-1 reduce, 512 splits -> 16 groups. grid (16,16), block 256.
// ---------------------------------------------------------------------------
__global__ void __launch_bounds__(256)
otpe_reduce1() {
    const int col = blockIdx.x * 256 + threadIdx.x;   // 0..4095
    const int g   = blockIdx.y;                        // 0..15
    const int s0  = g * SPLITS_PER_GROUP;

    float a0 = 0.f, a1 = 0.f, a2 = 0.f, a3 = 0.f;
#pragma unroll
    for (int s = 0; s < SPLITS_PER_GROUP; s += 4) {
        a0 += g_part[(size_t)(s0 + s + 0) * N_OUT + col];
        a1 += g_part[(size_t)(s0 + s + 1) * N_OUT + col];
        a2 += g_part[(size_t)(s0 + s + 2) * N_OUT + col];
        a3 += g_part[(size_t)(s0 + s + 3) * N_OUT + col];
    }
    g_part2[g * N_OUT + col] = (a0 + a1) + (a2 + a3);
}

// ---------------------------------------------------------------------------
// K2b: stage-2 reduce (16 groups) + per-column post. grid 16, block 256.
// ---------------------------------------------------------------------------
__global__ void __launch_bounds__(256)
otpe_column_post(const float* __restrict__ u,
                 const float* __restrict__ g_bar,
                 const float* __restrict__ ratio,
                 float* __restrict__ out_s,
                 float* __restrict__ out_u,
                 float* __restrict__ out_gbar,
                 float* __restrict__ out_ratio) {
    const int j = blockIdx.x * 256 + threadIdx.x;     // 0..4095

    float a0 = SIG_TAU * u[j], a1 = 0.f, a2 = 0.f, a3 = 0.f;
#pragma unroll
    for (int g = 0; g < NGROUP; g += 4) {
        a0 += g_part2[(g + 0) * N_OUT + j];
        a1 += g_part2[(g + 1) * N_OUT + j];
        a2 += g_part2[(g + 2) * N_OUT + j];
        a3 += g_part2[(g + 3) * N_OUT + j];
    }
    const float u_pre = (a0 + a1) + (a2 + a3);

    const float spike = (u_pre >= 1.0f) ? 1.0f : 0.0f;
    const float t  = fmaf(10.0f, fabsf(u_pre - 1.0f), 1.0f);
    const float sg = 1.0f / (t * t);

    g_sg[j]  = sg;
    out_s[j] = spike;
    out_u[j] = u_pre - spike;          // soft reset (V_TH = 1)

    const float r0        = SIG_TAU * ratio[0];
    const float ratio_new = r0 + 1.0f;
    const float r         = r0 / ratio_new;
    // ds_du_prev / sig_tau == sg
    out_gbar[j] = fmaf(r, g_bar[j], (1.0f - r) * sg);

    if (j == 0) out_ratio[0] = ratio_new;
}

// ---------------------------------------------------------------------------
// K3: fused E/R update, float4, 1 per thread.
// R_new = sig*R_hat + sg*E_new  (identity: sg*(sig*E + x) = ds_dtheta).
// grid 32768, block 256. Unchanged from R4 (82% DRAM).
// ---------------------------------------------------------------------------
__global__ void __launch_bounds__(256)
otpe_big_elem(const float4* __restrict__ E,
              const float4* __restrict__ R,
              const float*  __restrict__ x,
              float4* __restrict__ Eo,
              float4* __restrict__ Ro) {
    const long long v = (long long)blockIdx.x * 256 + threadIdx.x;
    const int row  = (int)(v >> 10);        // 1024 float4 per row
    const int colv = (int)(v & 1023);

    const float  xi  = __ldg(&x[row]);
    const float4 sg4 = reinterpret_cast<const float4*>(g_sg)[colv];
    const float4 e   = E[v];
    const float4 rr  = R[v];

    float4 eo, ro;
    eo.x = fmaf(SIG_TAU, e.x, xi);
    eo.y = fmaf(SIG_TAU, e.y, xi);
    eo.z = fmaf(SIG_TAU, e.z, xi);
    eo.w = fmaf(SIG_TAU, e.w, xi);

    ro.x = fmaf(sg4.x, eo.x, SIG_TAU * rr.x);
    ro.y = fmaf(sg4.y, eo.y, SIG_TAU * rr.y);
    ro.z = fmaf(sg4.z, eo.z, SIG_TAU * rr.z);
    ro.w = fmaf(sg4.w, eo.w, SIG_TAU * rr.w);

    Eo[v] = eo;
    Ro[v] = ro;
}

// ---------------------------------------------------------------------------
extern "C" void kernel_launch(void* const* d_in, const int* in_sizes, int n_in,
                              void* d_out, int out_size) {
    const float* x     = (const float*)d_in[0];
    const float* W     = (const float*)d_in[1];
    const float* u     = (const float*)d_in[2];
    const float* E     = (const float*)d_in[3];
    const float* R     = (const float*)d_in[4];
    const float* g_bar = (const float*)d_in[5];
    const float* ratio = (const float*)d_in[6];

    float* out       = (float*)d_out;
    float* out_s     = out;
    float* out_u     = out + N_OUT;
    float* out_E     = out + 2 * N_OUT;
    float* out_R     = out_E + (size_t)N_IN * N_OUT;
    float* out_gbar  = out_R + (size_t)N_IN * N_OUT;
    float* out_ratio = out_gbar + N_OUT;

    otpe_gemv_partial<<<dim3(2, NSPLIT), 256>>>((const float4*)W, x);
    otpe_reduce1<<<dim3(N_OUT / 256, NGROUP), 256>>>();
    otpe_column_post<<<N_OUT / 256, 256>>>(u, g_bar, ratio,
                                           out_s, out_u, out_gbar, out_ratio);

    const long long nvec = (long long)N_IN * N_OUT / 4;   // 8388608
    otpe_big_elem<<<(unsigned)(nvec / 256), 256>>>(
        (const float4*)E, (const float4*)R, x,
        (float4*)out_E, (float4*)out_R);
}

// round 6
// speedup vs baseline: 1.1801x; 1.0105x over previous
#include <cuda_runtime.h>

// ---------------------------------------------------------------------------
// OTPE single timestep.
// Inputs (metadata order): x[8192], W[8192,4096], u[4096], E[8192,4096],
//                          R_hat[8192,4096], g_bar[4096], ratio[1]
// Output (flattened tuple): s[4096], u_new[4096], E_new[8192*4096],
//                           R_new[8192*4096], g_bar_new[4096], ratio_new[1]
// ---------------------------------------------------------------------------

#define N_IN   8192
#define N_OUT  4096
#define N_OUTV (N_OUT / 4)               // 1024 float4 per row
// sigmoid(2.0) in fp32
#define SIG_TAU 0.88079707797788231f

#define NSPLIT 256
#define ROWS_PER_SPLIT (N_IN / NSPLIT)     // 32
#define NGROUP 16                          // stage-2 reduce groups
#define SPLITS_PER_GROUP (NSPLIT / NGROUP) // 16

#define GEMV_STAGES 8

// scratch (device globals; no allocation allowed)
__device__ __align__(16) float g_part[NSPLIT * N_OUT];    // 4 MB
__device__ __align__(16) float g_part2[NGROUP * N_OUT];   // 256 KB
__device__ __align__(16) float g_sg[N_OUT];

// ---------------------------------------------------------------------------
// K1: split-K GEMV via cp.async (LDGSTS .cg, L2-only) 8-stage pipeline.
// grid (4, 256) = 1024 blocks, block 256, 32KB smem.
// Thread t stages + consumes exactly tile[s][t] (its own float4 column) —
// no cross-thread smem sharing, so no __syncthreads in the mainloop.
// Rationale: LDG-path read streams cap at ~5.4TB/s; the async-copy path is
// LTS-cap path-independent (~6.3-7 TB/s).
// ---------------------------------------------------------------------------
__global__ void __launch_bounds__(256)
otpe_gemv_partial(const float4* __restrict__ W4, const float* __restrict__ x) {
    __shared__ __align__(16) float4 tile[GEMV_STAGES][256];
    __shared__ float sx[ROWS_PER_SPLIT];

    const int t     = threadIdx.x;
    const int split = blockIdx.y;
    const int r0    = split * ROWS_PER_SPLIT;
    const int colv  = blockIdx.x * 256 + t;

    if (t < ROWS_PER_SPLIT)
        sx[t] = x[r0 + t];
    __syncthreads();

    const float4* Wg = W4 + (size_t)r0 * N_OUTV + colv;

    // prologue: fill all 8 stages
#pragma unroll
    for (int s = 0; s < GEMV_STAGES; ++s) {
        unsigned dst = (unsigned)__cvta_generic_to_shared(&tile[s][t]);
        asm volatile("cp.async.cg.shared.global [%0], [%1], 16;\n"
                     :: "r"(dst), "l"(Wg + (size_t)s * N_OUTV));
        asm volatile("cp.async.commit_group;\n");
    }

    float4 A = make_float4(0.f, 0.f, 0.f, 0.f);
#pragma unroll
    for (int r = 0; r < ROWS_PER_SPLIT; ++r) {
        // allow <=7 pending groups -> the group for slot r&7 has landed
        asm volatile("cp.async.wait_group %0;\n" :: "n"(GEMV_STAGES - 1) : "memory");
        const float4 w  = tile[r & (GEMV_STAGES - 1)][t];
        const float  xr = sx[r];
        A.x = fmaf(xr, w.x, A.x);
        A.y = fmaf(xr, w.y, A.y);
        A.z = fmaf(xr, w.z, A.z);
        A.w = fmaf(xr, w.w, A.w);

        const int rn = r + GEMV_STAGES;
        if (rn < ROWS_PER_SPLIT) {
            unsigned dst = (unsigned)__cvta_generic_to_shared(
                &tile[r & (GEMV_STAGES - 1)][t]);
            asm volatile("cp.async.cg.shared.global [%0], [%1], 16;\n"
                         :: "r"(dst), "l"(Wg + (size_t)rn * N_OUTV));
        }
        // commit (possibly empty) to keep the group count aligned
        asm volatile("cp.async.commit_group;\n");
    }

    reinterpret_cast<float4*>(g_part)[(size_t)split * N_OUTV + colv] = A;
}

// ---------------------------------------------------------------------------
// K2a: stage-1 reduce, 256 splits -> 16 groups. grid (16,16), block 256.
// ---------------------------------------------------------------------------
__global__ void __launch_bounds__(256)
otpe_reduce1() {
    const int col = blockIdx.x * 256 + threadIdx.x;   // 0..4095
    const int g   = blockIdx.y;                        // 0..15
    const int s0  = g * SPLITS_PER_GROUP;

    float a0 = 0.f, a1 = 0.f, a2 = 0.f, a3 = 0.f;
#pragma unroll
    for (int s = 0; s < SPLITS_PER_GROUP; s += 4) {
        a0 += g_part[(size_t)(s0 + s + 0) * N_OUT + col];
        a1 += g_part[(size_t)(s0 + s + 1) * N_OUT + col];
        a2 += g_part[(size_t)(s0 + s + 2) * N_OUT + col];
        a3 += g_part[(size_t)(s0 + s + 3) * N_OUT + col];
    }
    g_part2[g * N_OUT + col] = (a0 + a1) + (a2 + a3);
}

// ---------------------------------------------------------------------------
// K2b: stage-2 reduce (16 groups) + per-column post. grid 16, block 256.
// ---------------------------------------------------------------------------
__global__ void __launch_bounds__(256)
otpe_column_post(const float* __restrict__ u,
                 const float* __restrict__ g_bar,
                 const float* __restrict__ ratio,
                 float* __restrict__ out_s,
                 float* __restrict__ out_u,
                 float* __restrict__ out_gbar,
                 float* __restrict__ out_ratio) {
    const int j = blockIdx.x * 256 + threadIdx.x;     // 0..4095

    float a0 = SIG_TAU * u[j], a1 = 0.f, a2 = 0.f, a3 = 0.f;
#pragma unroll
    for (int g = 0; g < NGROUP; g += 4) {
        a0 += g_part2[(g + 0) * N_OUT + j];
        a1 += g_part2[(g + 1) * N_OUT + j];
        a2 += g_part2[(g + 2) * N_OUT + j];
        a3 += g_part2[(g + 3) * N_OUT + j];
    }
    const float u_pre = (a0 + a1) + (a2 + a3);

    const float spike = (u_pre >= 1.0f) ? 1.0f : 0.0f;
    const float t  = fmaf(10.0f, fabsf(u_pre - 1.0f), 1.0f);
    const float sg = 1.0f / (t * t);

    g_sg[j]  = sg;
    out_s[j] = spike;
    out_u[j] = u_pre - spike;          // soft reset (V_TH = 1)

    const float r0        = SIG_TAU * ratio[0];
    const float ratio_new = r0 + 1.0f;
    const float r         = r0 / ratio_new;
    // ds_du_prev / sig_tau == sg
    out_gbar[j] = fmaf(r, g_bar[j], (1.0f - r) * sg);

    if (j == 0) out_ratio[0] = ratio_new;
}

// ---------------------------------------------------------------------------
// K3: fused E/R update, float4, 1 per thread. UNCHANGED (82% DRAM = ceiling).
// R_new = sig*R_hat + sg*E_new  (identity: sg*(sig*E + x) = ds_dtheta).
// grid 32768, block 256.
// ---------------------------------------------------------------------------
__global__ void __launch_bounds__(256)
otpe_big_elem(const float4* __restrict__ E,
              const float4* __restrict__ R,
              const float*  __restrict__ x,
              float4* __restrict__ Eo,
              float4* __restrict__ Ro) {
    const long long v = (long long)blockIdx.x * 256 + threadIdx.x;
    const int row  = (int)(v >> 10);        // 1024 float4 per row
    const int colv = (int)(v & 1023);

    const float  xi  = __ldg(&x[row]);
    const float4 sg4 = reinterpret_cast<const float4*>(g_sg)[colv];
    const float4 e   = E[v];
    const float4 rr  = R[v];

    float4 eo, ro;
    eo.x = fmaf(SIG_TAU, e.x, xi);
    eo.y = fmaf(SIG_TAU, e.y, xi);
    eo.z = fmaf(SIG_TAU, e.z, xi);
    eo.w = fmaf(SIG_TAU, e.w, xi);

    ro.x = fmaf(sg4.x, eo.x, SIG_TAU * rr.x);
    ro.y = fmaf(sg4.y, eo.y, SIG_TAU * rr.y);
    ro.z = fmaf(sg4.z, eo.z, SIG_TAU * rr.z);
    ro.w = fmaf(sg4.w, eo.w, SIG_TAU * rr.w);

    Eo[v] = eo;
    Ro[v] = ro;
}

// ---------------------------------------------------------------------------
extern "C" void kernel_launch(void* const* d_in, const int* in_sizes, int n_in,
                              void* d_out, int out_size) {
    const float* x     = (const float*)d_in[0];
    const float* W     = (const float*)d_in[1];
    const float* u     = (const float*)d_in[2];
    const float* E     = (const float*)d_in[3];
    const float* R     = (const float*)d_in[4];
    const float* g_bar = (const float*)d_in[5];
    const float* ratio = (const float*)d_in[6];

    float* out       = (float*)d_out;
    float* out_s     = out;
    float* out_u     = out + N_OUT;
    float* out_E     = out + 2 * N_OUT;
    float* out_R     = out_E + (size_t)N_IN * N_OUT;
    float* out_gbar  = out_R + (size_t)N_IN * N_OUT;
    float* out_ratio = out_gbar + N_OUT;

    otpe_gemv_partial<<<dim3(N_OUTV / 256, NSPLIT), 256>>>((const float4*)W, x);
    otpe_reduce1<<<dim3(N_OUT / 256, NGROUP), 256>>>();
    otpe_column_post<<<N_OUT / 256, 256>>>(u, g_bar, ratio,
                                           out_s, out_u, out_gbar, out_ratio);

    const long long nvec = (long long)N_IN * N_OUT / 4;   // 8388608
    otpe_big_elem<<<(unsigned)(nvec / 256), 256>>>(
        (const float4*)E, (const float4*)R, x,
        (float4*)out_E, (float4*)out_R);
}

// round 7
// speedup vs baseline: 1.1822x; 1.0018x over previous
#include <cuda_runtime.h>

// ---------------------------------------------------------------------------
// OTPE single timestep.
// Inputs (metadata order): x[8192], W[8192,4096], u[4096], E[8192,4096],
//                          R_hat[8192,4096], g_bar[4096], ratio[1]
// Output (flattened tuple): s[4096], u_new[4096], E_new[8192*4096],
//                           R_new[8192*4096], g_bar_new[4096], ratio_new[1]
// ---------------------------------------------------------------------------

#define N_IN   8192
#define N_OUT  4096
#define N_OUTV (N_OUT / 4)               // 1024 float4 per row
// sigmoid(2.0) in fp32
#define SIG_TAU 0.88079707797788231f

#define NSPLIT 256
#define ROWS_PER_SPLIT (N_IN / NSPLIT)     // 32

#define GEMV_STAGES 8

// scratch (device globals; no allocation allowed)
__device__ __align__(16) float g_part[NSPLIT * N_OUT];    // 4 MB
__device__ __align__(16) float g_sg[N_OUT];

// ---------------------------------------------------------------------------
// K1: split-K GEMV via cp.async (LDGSTS .cg, L2-only) 8-stage pipeline.
// grid (4, 256) = 1024 blocks, block 256, 32KB smem. (Unchanged from R6.)
// ---------------------------------------------------------------------------
__global__ void __launch_bounds__(256)
otpe_gemv_partial(const float4* __restrict__ W4, const float* __restrict__ x) {
    __shared__ __align__(16) float4 tile[GEMV_STAGES][256];
    __shared__ float sx[ROWS_PER_SPLIT];

    const int t     = threadIdx.x;
    const int split = blockIdx.y;
    const int r0    = split * ROWS_PER_SPLIT;
    const int colv  = blockIdx.x * 256 + t;

    if (t < ROWS_PER_SPLIT)
        sx[t] = x[r0 + t];
    __syncthreads();

    const float4* Wg = W4 + (size_t)r0 * N_OUTV + colv;

    // prologue: fill all 8 stages
#pragma unroll
    for (int s = 0; s < GEMV_STAGES; ++s) {
        unsigned dst = (unsigned)__cvta_generic_to_shared(&tile[s][t]);
        asm volatile("cp.async.cg.shared.global [%0], [%1], 16;\n"
                     :: "r"(dst), "l"(Wg + (size_t)s * N_OUTV));
        asm volatile("cp.async.commit_group;\n");
    }

    float4 A = make_float4(0.f, 0.f, 0.f, 0.f);
#pragma unroll
    for (int r = 0; r < ROWS_PER_SPLIT; ++r) {
        asm volatile("cp.async.wait_group %0;\n" :: "n"(GEMV_STAGES - 1) : "memory");
        const float4 w  = tile[r & (GEMV_STAGES - 1)][t];
        const float  xr = sx[r];
        A.x = fmaf(xr, w.x, A.x);
        A.y = fmaf(xr, w.y, A.y);
        A.z = fmaf(xr, w.z, A.z);
        A.w = fmaf(xr, w.w, A.w);

        const int rn = r + GEMV_STAGES;
        if (rn < ROWS_PER_SPLIT) {
            unsigned dst = (unsigned)__cvta_generic_to_shared(
                &tile[r & (GEMV_STAGES - 1)][t]);
            asm volatile("cp.async.cg.shared.global [%0], [%1], 16;\n"
                         :: "r"(dst), "l"(Wg + (size_t)rn * N_OUTV));
        }
        asm volatile("cp.async.commit_group;\n");
    }

    reinterpret_cast<float4*>(g_part)[(size_t)split * N_OUTV + colv] = A;
}

// ---------------------------------------------------------------------------
// K2: fused reduce (256 splits) + per-column post in ONE kernel.
// grid 64, block 256. Thread tid = k*64 + c: lane-group k (0..3) sums
// splits [k*64, k*64+64) for column blockIdx.x*64 + c (coalesced, L2-hit).
// Fixed-order smem combine keeps it deterministic.
// ---------------------------------------------------------------------------
__global__ void __launch_bounds__(256)
otpe_reduce_post(const float* __restrict__ u,
                 const float* __restrict__ g_bar,
                 const float* __restrict__ ratio,
                 float* __restrict__ out_s,
                 float* __restrict__ out_u,
                 float* __restrict__ out_gbar,
                 float* __restrict__ out_ratio) {
    __shared__ float sums[4][64];

    const int c   = threadIdx.x & 63;        // column within block
    const int k   = threadIdx.x >> 6;        // split group 0..3
    const int col = blockIdx.x * 64 + c;
    const int s0  = k * 64;

    float a0 = 0.f, a1 = 0.f, a2 = 0.f, a3 = 0.f;
#pragma unroll
    for (int s = 0; s < 64; s += 4) {
        a0 += g_part[(size_t)(s0 + s + 0) * N_OUT + col];
        a1 += g_part[(size_t)(s0 + s + 1) * N_OUT + col];
        a2 += g_part[(size_t)(s0 + s + 2) * N_OUT + col];
        a3 += g_part[(size_t)(s0 + s + 3) * N_OUT + col];
    }
    sums[k][c] = (a0 + a1) + (a2 + a3);
    __syncthreads();

    if (threadIdx.x < 64) {
        const int j = blockIdx.x * 64 + threadIdx.x;
        const float u_pre = fmaf(SIG_TAU, u[j],
            ((sums[0][threadIdx.x] + sums[1][threadIdx.x]) +
             (sums[2][threadIdx.x] + sums[3][threadIdx.x])));

        const float spike = (u_pre >= 1.0f) ? 1.0f : 0.0f;
        const float t  = fmaf(10.0f, fabsf(u_pre - 1.0f), 1.0f);
        const float sg = 1.0f / (t * t);

        g_sg[j]  = sg;
        out_s[j] = spike;
        out_u[j] = u_pre - spike;          // soft reset (V_TH = 1)

        const float r0        = SIG_TAU * ratio[0];
        const float ratio_new = r0 + 1.0f;
        const float r         = r0 / ratio_new;
        // ds_du_prev / sig_tau == sg
        out_gbar[j] = fmaf(r, g_bar[j], (1.0f - r) * sg);

        if (j == 0) out_ratio[0] = ratio_new;
    }
}

// ---------------------------------------------------------------------------
// K3: fused E/R update, float4, 1 per thread. Stores evict-streaming
// (__stcs ONLY on stores; loads untouched — isolating this variable).
// R_new = sig*R_hat + sg*E_new. grid 32768, block 256.
// ---------------------------------------------------------------------------
__global__ void __launch_bounds__(256)
otpe_big_elem(const float4* __restrict__ E,
              const float4* __restrict__ R,
              const float*  __restrict__ x,
              float4* __restrict__ Eo,
              float4* __restrict__ Ro) {
    const long long v = (long long)blockIdx.x * 256 + threadIdx.x;
    const int row  = (int)(v >> 10);        // 1024 float4 per row
    const int colv = (int)(v & 1023);

    const float  xi  = __ldg(&x[row]);
    const float4 sg4 = reinterpret_cast<const float4*>(g_sg)[colv];
    const float4 e   = E[v];
    const float4 rr  = R[v];

    float4 eo, ro;
    eo.x = fmaf(SIG_TAU, e.x, xi);
    eo.y = fmaf(SIG_TAU, e.y, xi);
    eo.z = fmaf(SIG_TAU, e.z, xi);
    eo.w = fmaf(SIG_TAU, e.w, xi);

    ro.x = fmaf(sg4.x, eo.x, SIG_TAU * rr.x);
    ro.y = fmaf(sg4.y, eo.y, SIG_TAU * rr.y);
    ro.z = fmaf(sg4.z, eo.z, SIG_TAU * rr.z);
    ro.w = fmaf(sg4.w, eo.w, SIG_TAU * rr.w);

    __stcs(&Eo[v], eo);
    __stcs(&Ro[v], ro);
}

// ---------------------------------------------------------------------------
extern "C" void kernel_launch(void* const* d_in, const int* in_sizes, int n_in,
                              void* d_out, int out_size) {
    const float* x     = (const float*)d_in[0];
    const float* W     = (const float*)d_in[1];
    const float* u     = (const float*)d_in[2];
    const float* E     = (const float*)d_in[3];
    const float* R     = (const float*)d_in[4];
    const float* g_bar = (const float*)d_in[5];
    const float* ratio = (const float*)d_in[6];

    float* out       = (float*)d_out;
    float* out_s     = out;
    float* out_u     = out + N_OUT;
    float* out_E     = out + 2 * N_OUT;
    float* out_R     = out_E + (size_t)N_IN * N_OUT;
    float* out_gbar  = out_R + (size_t)N_IN * N_OUT;
    float* out_ratio = out_gbar + N_OUT;

    otpe_gemv_partial<<<dim3(N_OUTV / 256, NSPLIT), 256>>>((const float4*)W, x);
    otpe_reduce_post<<<N_OUT / 64, 256>>>(u, g_bar, ratio,
                                          out_s, out_u, out_gbar, out_ratio);

    const long long nvec = (long long)N_IN * N_OUT / 4;   // 8388608
    otpe_big_elem<<<(unsigned)(nvec / 256), 256>>>(
        (const float4*)E, (const float4*)R, x,
        (float4*)out_E, (float4*)out_R);
}

// round 8
// speedup vs baseline: 1.2020x; 1.0167x over previous
#include <cuda_runtime.h>

// ---------------------------------------------------------------------------
// OTPE single timestep.
// Inputs (metadata order): x[8192], W[8192,4096], u[4096], E[8192,4096],
//                          R_hat[8192,4096], g_bar[4096], ratio[1]
// Output (flattened tuple): s[4096], u_new[4096], E_new[8192*4096],
//                           R_new[8192*4096], g_bar_new[4096], ratio_new[1]
// ---------------------------------------------------------------------------

#define N_IN   8192
#define N_OUT  4096
#define N_OUTV (N_OUT / 4)               // 1024 float4 per row
// sigmoid(2.0) in fp32
#define SIG_TAU 0.88079707797788231f

#define NSPLIT 256
#define ROWS_PER_SPLIT (N_IN / NSPLIT)     // 32

#define GEMV_STAGES 8

// scratch (device globals; no allocation allowed)
__device__ __align__(16) float g_part[NSPLIT * N_OUT];    // 4 MB
__device__ __align__(16) float g_sg[N_OUT];

// ---------------------------------------------------------------------------
// K1: split-K GEMV via cp.async (LDGSTS .cg) 8-stage pipeline.
// grid (4, 256) = 1024 blocks, block 256. (Unchanged — measured stream cap.)
// ---------------------------------------------------------------------------
__global__ void __launch_bounds__(256)
otpe_gemv_partial(const float4* __restrict__ W4, const float* __restrict__ x) {
    __shared__ __align__(16) float4 tile[GEMV_STAGES][256];
    __shared__ float sx[ROWS_PER_SPLIT];

    const int t     = threadIdx.x;
    const int split = blockIdx.y;
    const int r0    = split * ROWS_PER_SPLIT;
    const int colv  = blockIdx.x * 256 + t;

    if (t < ROWS_PER_SPLIT)
        sx[t] = x[r0 + t];
    __syncthreads();

    const float4* Wg = W4 + (size_t)r0 * N_OUTV + colv;

#pragma unroll
    for (int s = 0; s < GEMV_STAGES; ++s) {
        unsigned dst = (unsigned)__cvta_generic_to_shared(&tile[s][t]);
        asm volatile("cp.async.cg.shared.global [%0], [%1], 16;\n"
                     :: "r"(dst), "l"(Wg + (size_t)s * N_OUTV));
        asm volatile("cp.async.commit_group;\n");
    }

    float4 A = make_float4(0.f, 0.f, 0.f, 0.f);
#pragma unroll
    for (int r = 0; r < ROWS_PER_SPLIT; ++r) {
        asm volatile("cp.async.wait_group %0;\n" :: "n"(GEMV_STAGES - 1) : "memory");
        const float4 w  = tile[r & (GEMV_STAGES - 1)][t];
        const float  xr = sx[r];
        A.x = fmaf(xr, w.x, A.x);
        A.y = fmaf(xr, w.y, A.y);
        A.z = fmaf(xr, w.z, A.z);
        A.w = fmaf(xr, w.w, A.w);

        const int rn = r + GEMV_STAGES;
        if (rn < ROWS_PER_SPLIT) {
            unsigned dst = (unsigned)__cvta_generic_to_shared(
                &tile[r & (GEMV_STAGES - 1)][t]);
            asm volatile("cp.async.cg.shared.global [%0], [%1], 16;\n"
                         :: "r"(dst), "l"(Wg + (size_t)rn * N_OUTV));
        }
        asm volatile("cp.async.commit_group;\n");
    }

    reinterpret_cast<float4*>(g_part)[(size_t)split * N_OUTV + colv] = A;
}

// ---------------------------------------------------------------------------
// K2: fused reduce (256 splits) + per-column post. grid 64, block 256.
// PDL secondary: prefetch u/g_bar/ratio, THEN wait on K1, THEN read g_part.
// ---------------------------------------------------------------------------
__global__ void __launch_bounds__(256)
otpe_reduce_post(const float* __restrict__ u,
                 const float* __restrict__ g_bar,
                 const float* __restrict__ ratio,
                 float* __restrict__ out_s,
                 float* __restrict__ out_u,
                 float* __restrict__ out_gbar,
                 float* __restrict__ out_ratio) {
    __shared__ float sums[4][64];

    const int c   = threadIdx.x & 63;        // column within block
    const int k   = threadIdx.x >> 6;        // split group 0..3
    const int col = blockIdx.x * 64 + c;
    const int s0  = k * 64;
    const int j   = blockIdx.x * 64 + threadIdx.x;   // valid if tid<64

    // dependency-free prefetch (inputs only)
    float u_j = 0.f, gb_j = 0.f, ratio_in = 0.f;
    if (threadIdx.x < 64) {
        u_j      = u[j];
        gb_j     = g_bar[j];
        ratio_in = ratio[0];
    }

    cudaGridDependencySynchronize();   // K1's g_part now visible

    float a0 = 0.f, a1 = 0.f, a2 = 0.f, a3 = 0.f;
#pragma unroll
    for (int s = 0; s < 64; s += 4) {
        a0 += g_part[(size_t)(s0 + s + 0) * N_OUT + col];
        a1 += g_part[(size_t)(s0 + s + 1) * N_OUT + col];
        a2 += g_part[(size_t)(s0 + s + 2) * N_OUT + col];
        a3 += g_part[(size_t)(s0 + s + 3) * N_OUT + col];
    }
    sums[k][c] = (a0 + a1) + (a2 + a3);
    __syncthreads();

    if (threadIdx.x < 64) {
        const float u_pre = fmaf(SIG_TAU, u_j,
            ((sums[0][threadIdx.x] + sums[1][threadIdx.x]) +
             (sums[2][threadIdx.x] + sums[3][threadIdx.x])));

        const float spike = (u_pre >= 1.0f) ? 1.0f : 0.0f;
        const float t  = fmaf(10.0f, fabsf(u_pre - 1.0f), 1.0f);
        const float sg = 1.0f / (t * t);

        g_sg[j]  = sg;
        out_s[j] = spike;
        out_u[j] = u_pre - spike;          // soft reset (V_TH = 1)

        const float r0        = SIG_TAU * ratio_in;
        const float ratio_new = r0 + 1.0f;
        const float r         = r0 / ratio_new;
        // ds_du_prev / sig_tau == sg
        out_gbar[j] = fmaf(r, gb_j, (1.0f - r) * sg);

        if (j == 0) out_ratio[0] = ratio_new;
    }
}

// ---------------------------------------------------------------------------
// K3: fused E/R update, float4, 1 per thread. PDL secondary: prefetch
// E/R_hat/x (input-only, no hazard) BEFORE waiting on K2; read g_sg after.
// R_new = sig*R_hat + sg*E_new. Plain stores (stcs reverted).
// grid 32768, block 256.
// ---------------------------------------------------------------------------
__global__ void __launch_bounds__(256)
otpe_big_elem(const float4* __restrict__ E,
              const float4* __restrict__ R,
              const float*  __restrict__ x,
              float4* __restrict__ Eo,
              float4* __restrict__ Ro) {
    const long long v = (long long)blockIdx.x * 256 + threadIdx.x;
    const int row  = (int)(v >> 10);        // 1024 float4 per row
    const int colv = (int)(v & 1023);

    // dependency-free prefetch
    const float  xi = __ldg(&x[row]);
    const float4 e  = E[v];
    const float4 rr = R[v];

    cudaGridDependencySynchronize();   // K2's g_sg now visible

    const float4 sg4 = reinterpret_cast<const float4*>(g_sg)[colv];

    float4 eo, ro;
    eo.x = fmaf(SIG_TAU, e.x, xi);
    eo.y = fmaf(SIG_TAU, e.y, xi);
    eo.z = fmaf(SIG_TAU, e.z, xi);
    eo.w = fmaf(SIG_TAU, e.w, xi);

    ro.x = fmaf(sg4.x, eo.x, SIG_TAU * rr.x);
    ro.y = fmaf(sg4.y, eo.y, SIG_TAU * rr.y);
    ro.z = fmaf(sg4.z, eo.z, SIG_TAU * rr.z);
    ro.w = fmaf(sg4.w, eo.w, SIG_TAU * rr.w);

    Eo[v] = eo;
    Ro[v] = ro;
}

// ---------------------------------------------------------------------------
extern "C" void kernel_launch(void* const* d_in, const int* in_sizes, int n_in,
                              void* d_out, int out_size) {
    const float* x     = (const float*)d_in[0];
    const float* W     = (const float*)d_in[1];
    const float* u     = (const float*)d_in[2];
    const float* E     = (const float*)d_in[3];
    const float* R     = (const float*)d_in[4];
    const float* g_bar = (const float*)d_in[5];
    const float* ratio = (const float*)d_in[6];

    float* out       = (float*)d_out;
    float* out_s     = out;
    float* out_u     = out + N_OUT;
    float* out_E     = out + 2 * N_OUT;
    float* out_R     = out_E + (size_t)N_IN * N_OUT;
    float* out_gbar  = out_R + (size_t)N_IN * N_OUT;
    float* out_ratio = out_gbar + N_OUT;

    // K1: normal launch
    otpe_gemv_partial<<<dim3(N_OUTV / 256, NSPLIT), 256>>>((const float4*)W, x);

    // K2, K3: programmatic dependent launches (overlap launch/ramp with
    // predecessor; device-side cudaGridDependencySynchronize gates reads).
    cudaLaunchAttribute pdl[1];
    pdl[0].id = cudaLaunchAttributeProgrammaticStreamSerialization;
    pdl[0].val.programmaticStreamSerializationAllowed = 1;

    {
        cudaLaunchConfig_t cfg = {};
        cfg.gridDim  = dim3(N_OUT / 64);
        cfg.blockDim = dim3(256);
        cfg.stream   = 0;
        cfg.attrs    = pdl;
        cfg.numAttrs = 1;
        cudaLaunchKernelEx(&cfg, otpe_reduce_post, u, g_bar, ratio,
                           out_s, out_u, out_gbar, out_ratio);
    }
    {
        const long long nvec = (long long)N_IN * N_OUT / 4;   // 8388608
        cudaLaunchConfig_t cfg = {};
        cfg.gridDim  = dim3((unsigned)(nvec / 256));
        cfg.blockDim = dim3(256);
        cfg.stream   = 0;
        cfg.attrs    = pdl;
        cfg.numAttrs = 1;
        cudaLaunchKernelEx(&cfg, otpe_big_elem,
                           (const float4*)E, (const float4*)R, x,
                           (float4*)out_E, (float4*)out_R);
    }
}